// round 17
// baseline (speedup 1.0000x reference)
#include <cuda_runtime.h>
#include <cuda_fp16.h>
#include <cstdint>

#define NN 100000
#define NE 1600000
#define FDIM 64
#define NB_SCAN 98    // ceil(NN/1024)
#define GBLOCKS 1184  // persistent layer2 grid: 8 blocks/SM x 148 SMs

// ---------------- scratch (no allocation allowed) ----------------
__device__ float  g_B1[NN * FDIM];
__device__ float  g_B2[NN * FDIM];
__device__ float  g_B3[NN * FDIM];
__device__ __half g_Xh [NN * FDIM];   // prescaled fp16 gather copies (dinv ⊙ value)
__device__ __half g_B1h[NN * FDIM];
__device__ __half g_B2h[NN * FDIM];
__device__ float  g_Zv [NN * 8];      // layer-2 fp32 value buffers
__device__ float  g_T1v[NN * 8];
__device__ float  g_T2v[NN * 8];
__device__ __half g_Zsh [NN * 8];     // layer-2 prescaled fp16 gather copies
__device__ __half g_T1sh[NN * 8];
__device__ __half g_T2sh[NN * 8];
__device__ int    g_srcA[NE];         // CSR (by dst): src index only, 4B/edge
// fused zero region: [0,NN)=degS, [NN,2NN)=cntD, [2NN,2NN+98)=spine flags,
// [2NN+120]=layer2 grid-barrier counter
__device__ int    g_cnt[2 * NN + 128];
__device__ int    g_spineVal[128];    // flag-protected, needs no zeroing
__device__ int    g_rowStart[NN + 1];
__device__ int    g_cursor[NN];
__device__ float  g_dinv[NN];

__device__ __forceinline__ const float* pick(int s, const float* x) {
    switch (s) {
        case 1: return g_B1;
        case 2: return g_B2;
        case 3: return g_B3;
        default: return x;
    }
}
__device__ __forceinline__ float* pickw(int s, float* o) {
    switch (s) {
        case 1: return g_B1;
        case 2: return g_B2;
        case 3: return g_B3;
        default: return o;
    }
}
__device__ __forceinline__ const __half* pickh(int s) {
    switch (s) {
        case 1: return g_B1h;
        case 2: return g_B2h;
        default: return g_Xh;
    }
}

__device__ __forceinline__ uint32_t f2tf32(float x) {
    uint32_t u;
    asm("cvt.rna.tf32.f32 %0, %1;" : "=r"(u) : "f"(x));
    return u;
}

// ---------------- CSR build ----------------
__global__ void hist_kernel(const int* __restrict__ src, const int* __restrict__ dst) {
    for (int i = blockIdx.x * blockDim.x + threadIdx.x; i < NE / 4; i += gridDim.x * blockDim.x) {
        int4 s4 = ((const int4*)src)[i];
        int4 d4 = ((const int4*)dst)[i];
        atomicAdd(&g_cnt[s4.x], 1);      atomicAdd(&g_cnt[NN + d4.x], 1);
        atomicAdd(&g_cnt[s4.y], 1);      atomicAdd(&g_cnt[NN + d4.y], 1);
        atomicAdd(&g_cnt[s4.z], 1);      atomicAdd(&g_cnt[NN + d4.z], 1);
        atomicAdd(&g_cnt[s4.w], 1);      atomicAdd(&g_cnt[NN + d4.w], 1);
    }
}

// single-pass scan: dinv + local scan + spine lookback + rowStart/cursor init
__global__ void __launch_bounds__(1024) scanall_kernel() {
    __shared__ int sb[1024];
    __shared__ int spre[128];
    int tid = threadIdx.x;
    int b   = blockIdx.x;
    int i   = b * 1024 + tid;

    if (i < NN) {
        int d = g_cnt[i];                    // degS
        g_dinv[i] = (d > 0) ? rsqrtf((float)d) : 0.0f;
    }
    int v = (i < NN) ? g_cnt[NN + i] : 0;    // cntD
    sb[tid] = v;
    __syncthreads();
    for (int off = 1; off < 1024; off <<= 1) {
        int t = (tid >= off) ? sb[tid - off] : 0;
        __syncthreads();
        sb[tid] += t;
        __syncthreads();
    }
    if (tid == 1023) {
        g_spineVal[b] = sb[1023];
        __threadfence();
        atomicExch(&g_cnt[2 * NN + b], 1);   // release flag
    }
    if (tid < b) {
        volatile int* flag = &g_cnt[2 * NN + tid];
        while (*flag == 0) { }
        __threadfence();
        spre[tid] = g_spineVal[tid];
    }
    __syncthreads();
    int boff = 0;
    if (b > 0) {
        if (tid == 0) {
            int s = 0;
            for (int q = 0; q < b; q++) s += spre[q];
            sb[0] = s;
        }
        __syncthreads();
        boff = sb[0];
    }
    if (i < NN) {
        int r = sb[tid] - v + boff;
        if (tid == 0) r = boff;              // sb[0] was overwritten above
        g_rowStart[i] = r;
        g_cursor[i]   = r;
        if (i == NN - 1) g_rowStart[NN] = r + v;
    }
}

// scatter (src index only) + fused xscale: Xh = dinv ⊙ x in fp16
__global__ void scatter_kernel(const int* __restrict__ src, const int* __restrict__ dst,
                               const float* __restrict__ x) {
    int stride = gridDim.x * blockDim.x;
    for (int i = blockIdx.x * blockDim.x + threadIdx.x; i < NE / 4; i += stride) {
        int4 s4 = ((const int4*)src)[i];
        int4 d4 = ((const int4*)dst)[i];
        g_srcA[atomicAdd(&g_cursor[d4.x], 1)] = s4.x;
        g_srcA[atomicAdd(&g_cursor[d4.y], 1)] = s4.y;
        g_srcA[atomicAdd(&g_cursor[d4.z], 1)] = s4.z;
        g_srcA[atomicAdd(&g_cursor[d4.w], 1)] = s4.w;
    }
    for (int i = blockIdx.x * blockDim.x + threadIdx.x; i < NN * 32; i += stride) {
        float d = g_dinv[i >> 5];
        float2 v = ((const float2*)x)[i];
        ((__half2*)g_Xh)[i] = __float22half2_rn(make_float2(d * v.x, d * v.y));
    }
}

// ---------------- 64-wide propagation (prescaled fp16 gather) ----------------
__device__ __forceinline__ void acc_row(float* acc, uint4 v) {
    float2 p0 = __half22float2(*(__half2*)&v.x);
    float2 p1 = __half22float2(*(__half2*)&v.y);
    float2 p2 = __half22float2(*(__half2*)&v.z);
    float2 p3 = __half22float2(*(__half2*)&v.w);
    acc[0] += p0.x; acc[1] += p0.y;
    acc[2] += p1.x; acc[3] += p1.y;
    acc[4] += p2.x; acc[5] += p2.y;
    acc[6] += p3.x; acc[7] += p3.y;
}

__global__ void __launch_bounds__(256, 8) prop64_kernel(
    const float* __restrict__ xin, int hsel, int psel, int osel, int whsel,
    float a, float b)
{
    const __half* hh  = pickh(hsel);
    const float* prev = pick(psel, xin);
    float* out        = pickw(osel, nullptr);
    __half* outh      = (whsel == 1) ? g_B1h : (whsel == 2) ? g_B2h : nullptr;

    int warp = (blockIdx.x * blockDim.x + threadIdx.x) >> 5;
    int lane = threadIdx.x & 31;
    int sub  = lane >> 3;
    int l8   = lane & 7;
    int n    = warp * 4 + sub;
    if (n >= NN) return;

    int s = g_rowStart[n];
    int e = g_rowStart[n + 1];

    float acc[8];
#pragma unroll
    for (int q = 0; q < 8; q++) acc[q] = 0.0f;

    int j = s;
    for (; j < e && (j & 3); j++) {
        int srci = g_srcA[j];
        uint4 v = *(const uint4*)(hh + (size_t)srci * FDIM + l8 * 8);
        acc_row(acc, v);
    }
    int e8 = j + ((e - j) & ~7);
    for (; j < e8; j += 8) {
        int4 c0 = *(const int4*)&g_srcA[j];
        int4 c1 = *(const int4*)&g_srcA[j + 4];
        uint4 v0 = *(const uint4*)(hh + (size_t)c0.x * FDIM + l8 * 8);
        uint4 v1 = *(const uint4*)(hh + (size_t)c0.y * FDIM + l8 * 8);
        uint4 v2 = *(const uint4*)(hh + (size_t)c0.z * FDIM + l8 * 8);
        uint4 v3 = *(const uint4*)(hh + (size_t)c0.w * FDIM + l8 * 8);
        uint4 v4 = *(const uint4*)(hh + (size_t)c1.x * FDIM + l8 * 8);
        uint4 v5 = *(const uint4*)(hh + (size_t)c1.y * FDIM + l8 * 8);
        uint4 v6 = *(const uint4*)(hh + (size_t)c1.z * FDIM + l8 * 8);
        uint4 v7 = *(const uint4*)(hh + (size_t)c1.w * FDIM + l8 * 8);
        acc_row(acc, v0); acc_row(acc, v1); acc_row(acc, v2); acc_row(acc, v3);
        acc_row(acc, v4); acc_row(acc, v5); acc_row(acc, v6); acc_row(acc, v7);
    }
    int e4 = j + ((e - j) & ~3);
    for (; j < e4; j += 4) {
        int4 c = *(const int4*)&g_srcA[j];
        uint4 v0 = *(const uint4*)(hh + (size_t)c.x * FDIM + l8 * 8);
        uint4 v1 = *(const uint4*)(hh + (size_t)c.y * FDIM + l8 * 8);
        uint4 v2 = *(const uint4*)(hh + (size_t)c.z * FDIM + l8 * 8);
        uint4 v3 = *(const uint4*)(hh + (size_t)c.w * FDIM + l8 * 8);
        acc_row(acc, v0); acc_row(acc, v1); acc_row(acc, v2); acc_row(acc, v3);
    }
    for (; j < e; j++) {
        int srci = g_srcA[j];
        uint4 v = *(const uint4*)(hh + (size_t)srci * FDIM + l8 * 8);
        acc_row(acc, v);
    }

    float dn = g_dinv[n];
    float aa = -a * dn;
    float r[8];
#pragma unroll
    for (int q = 0; q < 8; q++) r[q] = aa * acc[q];
    if (b != 0.0f) {
        const float4* p4 = (const float4*)(prev + (size_t)n * FDIM + l8 * 8);
        float4 p0 = p4[0], p1 = p4[1];
        r[0] += b * p0.x; r[1] += b * p0.y; r[2] += b * p0.z; r[3] += b * p0.w;
        r[4] += b * p1.x; r[5] += b * p1.y; r[6] += b * p1.z; r[7] += b * p1.w;
    }

    float4* o4 = (float4*)(out + (size_t)n * FDIM + l8 * 8);
    o4[0] = make_float4(r[0], r[1], r[2], r[3]);
    o4[1] = make_float4(r[4], r[5], r[6], r[7]);

    if (outh) {
        uint4 hv;
        *(__half2*)&hv.x = __float22half2_rn(make_float2(dn * r[0], dn * r[1]));
        *(__half2*)&hv.y = __float22half2_rn(make_float2(dn * r[2], dn * r[3]));
        *(__half2*)&hv.z = __float22half2_rn(make_float2(dn * r[4], dn * r[5]));
        *(__half2*)&hv.w = __float22half2_rn(make_float2(dn * r[6], dn * r[7]));
        *(uint4*)(outh + (size_t)n * FDIM + l8 * 8) = hv;
    }
}

// ---------------- layer 2: one persistent kernel, 3 phases + grid barriers ----------------
__device__ __forceinline__ void gridbar(int target) {
    __syncthreads();
    if (threadIdx.x == 0) {
        __threadfence();
        atomicAdd(&g_cnt[2 * NN + 120], 1);
        volatile int* c = &g_cnt[2 * NN + 120];
        while (*c < target) { }
        __threadfence();
    }
    __syncthreads();
}

// one 8-wide propagation sweep (grid-stride, 8 nodes/warp, 4 lanes/node)
__device__ void prop8_phase(const __half* __restrict__ h, const float* __restrict__ prev,
                            float* __restrict__ ov, __half* __restrict__ os,
                            float a, float b, int fuse, float* __restrict__ fout)
{
    int gtid  = blockIdx.x * blockDim.x + threadIdx.x;
    int lane  = threadIdx.x & 31;
    int sub   = lane >> 2;
    int l4    = lane & 3;
    int nwarp = (GBLOCKS * 256) >> 5;
    unsigned smask = 0xFu << (sub * 4);

    for (int n = (gtid >> 5) * 8 + sub; n < NN; n += nwarp * 8) {
        int s = g_rowStart[n];
        int e = g_rowStart[n + 1];

        float ax = 0.0f, ay = 0.0f;
        int j  = s;
        int e4 = s + ((e - s) & ~3);
        for (; j < e4; j += 4) {
            int c0 = g_srcA[j + 0];
            int c1 = g_srcA[j + 1];
            int c2 = g_srcA[j + 2];
            int c3 = g_srcA[j + 3];
            float2 v0 = __half22float2(*(const __half2*)(h + (size_t)c0 * 8 + l4 * 2));
            float2 v1 = __half22float2(*(const __half2*)(h + (size_t)c1 * 8 + l4 * 2));
            float2 v2 = __half22float2(*(const __half2*)(h + (size_t)c2 * 8 + l4 * 2));
            float2 v3 = __half22float2(*(const __half2*)(h + (size_t)c3 * 8 + l4 * 2));
            ax += v0.x + v1.x + v2.x + v3.x;
            ay += v0.y + v1.y + v2.y + v3.y;
        }
        for (; j < e; j++) {
            float2 v = __half22float2(*(const __half2*)(h + (size_t)g_srcA[j] * 8 + l4 * 2));
            ax += v.x; ay += v.y;
        }

        float dn = g_dinv[n];
        float aa = -a * dn;
        float rx = aa * ax, ry = aa * ay;
        if (b != 0.0f) {
            float2 p = *(const float2*)(prev + (size_t)n * 8 + l4 * 2);
            rx += b * p.x; ry += b * p.y;
        }

        if (!fuse) {
            *(float2*)(ov + (size_t)n * 8 + l4 * 2) = make_float2(rx, ry);
            ((__half2*)(os + (size_t)n * 8))[l4] =
                __float22half2_rn(make_float2(dn * rx, dn * ry));
        } else {
            // r = t3[n, 2*l4..2*l4+1]; cols 6,7 live in subgroup lane 3
            float t36 = __shfl_sync(smask, rx, 3, 4);
            float t37 = __shfl_sync(smask, ry, 3, 4);
            if (l4 == 0) {
                float o0 = t36 + g_T2v[(size_t)n * 8 + 4] + g_T1v[(size_t)n * 8 + 2]
                         + g_Zv[(size_t)n * 8 + 0];
                float o1 = t37 + g_T2v[(size_t)n * 8 + 5] + g_T1v[(size_t)n * 8 + 3]
                         + g_Zv[(size_t)n * 8 + 1];
                fout[(size_t)n * 2 + 0] = o0;
                fout[(size_t)n * 2 + 1] = o1;
            }
        }
    }
}

__global__ void __launch_bounds__(256, 8) layer2_kernel(float* __restrict__ out) {
    prop8_phase(g_Zsh,  g_Zv,  g_T1v, g_T1sh, 1.0f,  0.0f, 0, nullptr);  // T1 = L Z
    gridbar(GBLOCKS);
    prop8_phase(g_T1sh, g_Zv,  g_T2v, g_T2sh, 2.0f, -1.0f, 0, nullptr);  // T2 = 2 L T1 - Z
    gridbar(2 * GBLOCKS);
    prop8_phase(g_T2sh, g_T1v, nullptr, nullptr, 2.0f, -1.0f, 1, out);   // t3 fused -> out
}

// ---------------- layer-1 combine via tf32 mma.sync (+fused Z projection) ----------------
#define SMS 68
__global__ void __launch_bounds__(256) combine64_kernel(
    const float* __restrict__ xin, int s0, int s1, int s2, int s3,
    const float* __restrict__ W, const float* __restrict__ W2)
{
    __shared__ float sW[64 * SMS];
    __shared__ float sT[64 * SMS];
    __shared__ float sW2[512];
    __shared__ float sZ[64][4][8];

    const float* ts0 = pick(s0, xin);
    const float* ts1 = pick(s1, xin);
    const float* ts2 = pick(s2, xin);
    const float* ts3 = pick(s3, xin);

    int tid  = threadIdx.x;
    int wid  = tid >> 5;
    int lane = tid & 31;
    int g    = lane >> 2;
    int t4   = lane & 3;
    int R0   = (wid >> 1) * 16;
    int C0   = (wid & 1) * 32;
    int n0   = blockIdx.x * 64;

    for (int i = tid; i < 512; i += 256) sW2[i] = W2[i];

    float acc[4][4];
#pragma unroll
    for (int nt = 0; nt < 4; nt++)
#pragma unroll
        for (int q = 0; q < 4; q++) acc[nt][q] = 0.0f;

#pragma unroll
    for (int k = 0; k < 4; k++) {
        const float* tk = (k == 0) ? ts0 : (k == 1) ? ts1 : (k == 2) ? ts2 : ts3;
        const float* Wk = W + k * 4096;
#pragma unroll
        for (int i = tid; i < 4096; i += 256) {
            int r = i >> 6, c = i & 63;
            sW[r * SMS + c] = __uint_as_float(f2tf32(Wk[i]));
            int node = n0 + r;
            float tv = (node < NN) ? tk[(size_t)node * 64 + c] : 0.0f;
            sT[r * SMS + c] = __uint_as_float(f2tf32(tv));
        }
        __syncthreads();

#pragma unroll
        for (int kk = 0; kk < 8; kk++) {
            int kb = kk * 8;
            uint32_t a0 = __float_as_uint(sT[(R0 + g)     * SMS + kb + t4]);
            uint32_t a1 = __float_as_uint(sT[(R0 + g + 8) * SMS + kb + t4]);
            uint32_t a2 = __float_as_uint(sT[(R0 + g)     * SMS + kb + t4 + 4]);
            uint32_t a3 = __float_as_uint(sT[(R0 + g + 8) * SMS + kb + t4 + 4]);
#pragma unroll
            for (int nt = 0; nt < 4; nt++) {
                int col = C0 + nt * 8 + g;
                uint32_t b0 = __float_as_uint(sW[(kb + t4)     * SMS + col]);
                uint32_t b1 = __float_as_uint(sW[(kb + t4 + 4) * SMS + col]);
                asm volatile(
                    "mma.sync.aligned.m16n8k8.row.col.f32.tf32.tf32.f32 "
                    "{%0,%1,%2,%3}, {%4,%5,%6,%7}, {%8,%9}, {%0,%1,%2,%3};"
                    : "+f"(acc[nt][0]), "+f"(acc[nt][1]),
                      "+f"(acc[nt][2]), "+f"(acc[nt][3])
                    : "r"(a0), "r"(a1), "r"(a2), "r"(a3), "r"(b0), "r"(b1));
            }
        }
        __syncthreads();
    }

#pragma unroll
    for (int nt = 0; nt < 4; nt++) {
        int c0c = C0 + nt * 8 + 2 * t4;
        int r0  = R0 + g;
        int r1  = R0 + g + 8;
        sT[r0 * SMS + c0c]     = fmaxf(acc[nt][0], 0.f);
        sT[r0 * SMS + c0c + 1] = fmaxf(acc[nt][1], 0.f);
        sT[r1 * SMS + c0c]     = fmaxf(acc[nt][2], 0.f);
        sT[r1 * SMS + c0c + 1] = fmaxf(acc[nt][3], 0.f);
    }
    __syncthreads();

    int nodeL = tid >> 2;
    int jq    = tid & 3;
    float z[8];
#pragma unroll
    for (int r = 0; r < 8; r++) z[r] = 0.0f;
#pragma unroll
    for (int q = 0; q < 16; q++) {
        int i = jq * 16 + q;
        float hv = sT[nodeL * SMS + i];
#pragma unroll
        for (int kk = 0; kk < 4; kk++) {
            z[2 * kk + 0] += hv * sW2[kk * 128 + i * 2 + 0];
            z[2 * kk + 1] += hv * sW2[kk * 128 + i * 2 + 1];
        }
    }
#pragma unroll
    for (int r = 0; r < 8; r++) sZ[nodeL][jq][r] = z[r];
    __syncthreads();
    int n = n0 + nodeL;
    if (jq == 0 && n < NN) {
        float zr[8];
#pragma unroll
        for (int r = 0; r < 8; r++)
            zr[r] = sZ[nodeL][0][r] + sZ[nodeL][1][r] + sZ[nodeL][2][r] + sZ[nodeL][3][r];
        float dn = g_dinv[n];
        float4* zv = (float4*)(g_Zv + (size_t)n * 8);
        zv[0] = make_float4(zr[0], zr[1], zr[2], zr[3]);
        zv[1] = make_float4(zr[4], zr[5], zr[6], zr[7]);
        uint4 hz;
        *(__half2*)&hz.x = __float22half2_rn(make_float2(dn * zr[0], dn * zr[1]));
        *(__half2*)&hz.y = __float22half2_rn(make_float2(dn * zr[2], dn * zr[3]));
        *(__half2*)&hz.z = __float22half2_rn(make_float2(dn * zr[4], dn * zr[5]));
        *(__half2*)&hz.w = __float22half2_rn(make_float2(dn * zr[6], dn * zr[7]));
        *(uint4*)(g_Zsh + (size_t)n * 8) = hz;
    }
}

// ---------------- launcher ----------------
extern "C" void kernel_launch(void* const* d_in, const int* in_sizes, int n_in,
                              void* d_out, int out_size)
{
    const float* x   = (const float*)d_in[0];
    const int*   ei  = (const int*)d_in[1];
    const int*   src = ei;
    const int*   dst = ei + NE;
    const float* W1  = (const float*)d_in[2];
    const float* W2  = (const float*)d_in[3];
    float* out = (float*)d_out;

    const int TB = 256;
    int gP  = ((NN / 4) * 32 + TB - 1) / TB;   // prop64: 4 nodes/warp
    int gC  = (NN + 63) / 64;
    int gS  = 1184;

    // zero counters+flags+barrier via memset node (NOT a kernel launch)
    void* cntAddr = nullptr;
    cudaGetSymbolAddress(&cntAddr, g_cnt);
    cudaMemsetAsync(cntAddr, 0, (2 * NN + 128) * sizeof(int), 0);

    // ---- CSR build ----
    hist_kernel<<<gS, TB>>>(src, dst);         // launch 1
    scanall_kernel<<<NB_SCAN, 1024>>>();       // launch 2
    scatter_kernel<<<gS, TB>>>(src, dst, x);   // launch 3 (+xscale)

    // ---- layer 1 ----
    prop64_kernel<<<gP, TB>>>(x, 0, 0, 1, 1, 1.0f,  0.0f);  // launch 4 <- ncu window
    prop64_kernel<<<gP, TB>>>(x, 1, 0, 2, 2, 2.0f, -1.0f);
    prop64_kernel<<<gP, TB>>>(x, 2, 1, 3, 0, 2.0f, -1.0f);
    combine64_kernel<<<gC, TB>>>(x, 0, 1, 2, 3, W1, W2);    // Zv, Zsh

    // ---- layer 2: single persistent kernel, 3 phases ----
    layer2_kernel<<<GBLOCKS, TB>>>(out);
}